// round 1
// baseline (speedup 1.0000x reference)
#include <cuda_runtime.h>
#include <math.h>

#define B_  2
#define N_  2048
#define D_  1024
#define H_  16
#define HD_ 64
#define TD_ 3072          // 3*D
#define M_  (B_*N_)       // 4096

// Scratch (device globals: allowed; no runtime allocation)
__device__ float g_qkv[B_ * N_ * TD_];   // (B,N,3D) row-major
__device__ float g_cp [B_ * H_ * N_];    // coord_proj (b,h,n)

// ---------------------------------------------------------------------------
// QKV GEMM: C[4096,3072] = x[4096,1024] @ W[1024,3072] + bias
// 128x128 block tile, BK=16, 256 threads, 8x8 per-thread micro-tile.
// ---------------------------------------------------------------------------
__global__ __launch_bounds__(256)
void qkv_gemm_kernel(const float* __restrict__ A,
                     const float* __restrict__ W,
                     const float* __restrict__ bias)
{
    __shared__ float As[16][128];   // transposed A tile: As[k][m]
    __shared__ float Bs[16][128];   // Bs[k][n]

    const int K  = D_;
    const int Nn = TD_;
    const int bx = blockIdx.x;      // over Nn (24)
    const int by = blockIdx.y;      // over M  (32)
    const int tid = threadIdx.x;
    const int tr = tid >> 4;        // 0..15
    const int tc = tid & 15;        // 0..15

    float acc[8][8];
#pragma unroll
    for (int i = 0; i < 8; i++)
#pragma unroll
        for (int j = 0; j < 8; j++) acc[i][j] = 0.f;

    const int aRow = tid >> 2;            // 0..63
    const int aCol = (tid & 3) << 2;      // 0,4,8,12
    const int bRow = tid >> 5;            // 0..7
    const int bCol = (tid & 31) << 2;     // 0..124

    const float* Ap = A + (size_t)by * 128 * K;
    const float* Wp = W + bx * 128;
    float* C = g_qkv;

    for (int k0 = 0; k0 < K; k0 += 16) {
#pragma unroll
        for (int p = 0; p < 2; p++) {
            int r = aRow + p * 64;
            float4 v = *(const float4*)(Ap + (size_t)r * K + k0 + aCol);
            As[aCol + 0][r] = v.x;
            As[aCol + 1][r] = v.y;
            As[aCol + 2][r] = v.z;
            As[aCol + 3][r] = v.w;
        }
#pragma unroll
        for (int p = 0; p < 2; p++) {
            int r = bRow + p * 8;
            *(float4*)(&Bs[r][bCol]) =
                *(const float4*)(Wp + (size_t)(k0 + r) * Nn + bCol);
        }
        __syncthreads();

#pragma unroll
        for (int kk = 0; kk < 16; kk++) {
            float ra[8], rb[8];
            *(float4*)(ra)     = *(const float4*)(&As[kk][tr * 8]);
            *(float4*)(ra + 4) = *(const float4*)(&As[kk][tr * 8 + 4]);
            *(float4*)(rb)     = *(const float4*)(&Bs[kk][tc * 8]);
            *(float4*)(rb + 4) = *(const float4*)(&Bs[kk][tc * 8 + 4]);
#pragma unroll
            for (int i = 0; i < 8; i++)
#pragma unroll
                for (int j = 0; j < 8; j++)
                    acc[i][j] += ra[i] * rb[j];
        }
        __syncthreads();
    }

#pragma unroll
    for (int i = 0; i < 8; i++) {
        int row = by * 128 + tr * 8 + i;
#pragma unroll
        for (int j = 0; j < 8; j += 4) {
            int col = bx * 128 + tc * 8 + j;
            float4 v;
            v.x = acc[i][j + 0] + bias[col + 0];
            v.y = acc[i][j + 1] + bias[col + 1];
            v.z = acc[i][j + 2] + bias[col + 2];
            v.w = acc[i][j + 3] + bias[col + 3];
            *(float4*)(&C[(size_t)row * Nn + col]) = v;
        }
    }
}

// ---------------------------------------------------------------------------
// coord_proj[b,h,n] = coords[b,n,:] . rel_weight[h,:]   (CD = 3)
// ---------------------------------------------------------------------------
__global__ void coord_kernel(const float* __restrict__ coords,
                             const float* __restrict__ rw)
{
    int idx = blockIdx.x * blockDim.x + threadIdx.x;   // b*H*N
    if (idx >= B_ * H_ * N_) return;
    int n = idx % N_;
    int h = (idx / N_) % H_;
    int b = idx / (N_ * H_);
    const float* c = coords + ((size_t)b * N_ + n) * 3;
    const float* w = rw + h * 3;
    g_cp[idx] = c[0] * w[0] + c[1] * w[1] + c[2] * w[2];
}

// ---------------------------------------------------------------------------
// Flash attention, fp32. BM=BN=64, 256 threads, 4x4 micro-tiles.
// score = (q.k)/8 - cp[k] + bias[q,k]   (+cp[q] dropped: softmax shift-invariant)
// smem (dynamic, 66048 B): Qs[64][64] | Ks[64][65] | Vs[64][64] | Ps[64][65]
// ---------------------------------------------------------------------------
__global__ __launch_bounds__(256)
void attn_kernel(const float* __restrict__ bias2d, float* __restrict__ out)
{
    extern __shared__ float sm[];
    float (*Qs)[64] = (float (*)[64])(sm);            // 4096 floats
    float (*Ks)[65] = (float (*)[65])(sm + 4096);     // 4160
    float (*Vs)[64] = (float (*)[64])(sm + 8256);     // 4096
    float (*Ps)[65] = (float (*)[65])(sm + 12352);    // 4160

    const int bh = blockIdx.y;          // b*H + h  (0..31)
    const int b  = bh >> 4;
    const int h  = bh & 15;
    const int q0 = blockIdx.x * 64;
    const int tid = threadIdx.x;
    const int tr = tid >> 4;            // 0..15 (row group: 4 q rows)
    const int tc = tid & 15;            // 0..15 (col group: 4 cols)

    // base pointer to this head's Q columns inside g_qkv rows
    const float* qbase = g_qkv + (size_t)(b * N_) * TD_ + h * HD_;
    const float* cpb   = g_cp + (size_t)bh * N_;

    // ---- load Q tile (scaled by 1/sqrt(hd) = 0.125) ----
#pragma unroll
    for (int p = 0; p < 4; p++) {
        int idx = tid + p * 256;        // 0..1023
        int row = idx >> 4;
        int c4  = (idx & 15) << 2;
        float4 v = *(const float4*)(qbase + (size_t)(q0 + row) * TD_ + c4);
        v.x *= 0.125f; v.y *= 0.125f; v.z *= 0.125f; v.w *= 0.125f;
        *(float4*)(&Qs[row][c4]) = v;
    }

    float O[4][4];
    float m[4], l[4];
#pragma unroll
    for (int i = 0; i < 4; i++) {
        m[i] = -1e30f; l[i] = 0.f;
#pragma unroll
        for (int x = 0; x < 4; x++) O[i][x] = 0.f;
    }

    for (int k0 = 0; k0 < N_; k0 += 64) {
        __syncthreads();   // protect Ks/Vs vs previous iteration's readers

        // ---- load K, V tiles ----
#pragma unroll
        for (int p = 0; p < 4; p++) {
            int idx = tid + p * 256;
            int row = idx >> 4;
            int c4  = (idx & 15) << 2;
            const float* src = qbase + (size_t)(k0 + row) * TD_;
            float4 kv = *(const float4*)(src + 1024 + c4);
            Ks[row][c4 + 0] = kv.x; Ks[row][c4 + 1] = kv.y;
            Ks[row][c4 + 2] = kv.z; Ks[row][c4 + 3] = kv.w;
            float4 vv = *(const float4*)(src + 2048 + c4);
            *(float4*)(&Vs[row][c4]) = vv;
        }
        __syncthreads();

        // ---- S = Qs @ Ks^T ----
        float S[4][4];
#pragma unroll
        for (int i = 0; i < 4; i++)
#pragma unroll
            for (int j = 0; j < 4; j++) S[i][j] = 0.f;

#pragma unroll 8
        for (int d = 0; d < 64; d++) {
            float ra[4], rb[4];
#pragma unroll
            for (int i = 0; i < 4; i++) ra[i] = Qs[tr * 4 + i][d];
#pragma unroll
            for (int j = 0; j < 4; j++) rb[j] = Ks[tc * 4 + j][d];
#pragma unroll
            for (int i = 0; i < 4; i++)
#pragma unroll
                for (int j = 0; j < 4; j++)
                    S[i][j] += ra[i] * rb[j];
        }

        // ---- add bias[q,k] - cp[k] ----
        float cpj[4];
#pragma unroll
        for (int j = 0; j < 4; j++) cpj[j] = __ldg(cpb + k0 + tc * 4 + j);
#pragma unroll
        for (int i = 0; i < 4; i++) {
            const float4 bv = *(const float4*)(bias2d +
                (size_t)(q0 + tr * 4 + i) * N_ + k0 + tc * 4);
            S[i][0] += bv.x - cpj[0];
            S[i][1] += bv.y - cpj[1];
            S[i][2] += bv.z - cpj[2];
            S[i][3] += bv.w - cpj[3];
        }

        // ---- online softmax ----
#pragma unroll
        for (int i = 0; i < 4; i++) {
            float mx = fmaxf(fmaxf(S[i][0], S[i][1]), fmaxf(S[i][2], S[i][3]));
#pragma unroll
            for (int s = 8; s >= 1; s >>= 1)
                mx = fmaxf(mx, __shfl_xor_sync(0xffffffffu, mx, s));
            float mn = fmaxf(m[i], mx);
            float alpha = __expf(m[i] - mn);
            m[i] = mn;
            float rs = 0.f;
#pragma unroll
            for (int j = 0; j < 4; j++) {
                S[i][j] = __expf(S[i][j] - mn);
                rs += S[i][j];
            }
#pragma unroll
            for (int s = 8; s >= 1; s >>= 1)
                rs += __shfl_xor_sync(0xffffffffu, rs, s);
            l[i] = l[i] * alpha + rs;
#pragma unroll
            for (int x = 0; x < 4; x++) O[i][x] *= alpha;
#pragma unroll
            for (int j = 0; j < 4; j++)
                Ps[tr * 4 + i][tc * 4 + j] = S[i][j];
        }
        __syncthreads();

        // ---- O += P @ V ----
#pragma unroll 4
        for (int j = 0; j < 64; j++) {
            float pa[4];
#pragma unroll
            for (int i = 0; i < 4; i++) pa[i] = Ps[tr * 4 + i][j];
            const float4 vb = *(const float4*)(&Vs[j][tc * 4]);
#pragma unroll
            for (int i = 0; i < 4; i++) {
                O[i][0] += pa[i] * vb.x;
                O[i][1] += pa[i] * vb.y;
                O[i][2] += pa[i] * vb.z;
                O[i][3] += pa[i] * vb.w;
            }
        }
    }

    // ---- epilogue: normalize and write (B,N,H,hd) -> (B,N,D) ----
#pragma unroll
    for (int i = 0; i < 4; i++) {
        float inv = 1.0f / l[i];
        int q = q0 + tr * 4 + i;
        float4 ov;
        ov.x = O[i][0] * inv; ov.y = O[i][1] * inv;
        ov.z = O[i][2] * inv; ov.w = O[i][3] * inv;
        *(float4*)(&out[((size_t)(b * N_) + q) * D_ + h * HD_ + tc * 4]) = ov;
    }
}

// ---------------------------------------------------------------------------
extern "C" void kernel_launch(void* const* d_in, const int* in_sizes, int n_in,
                              void* d_out, int out_size)
{
    const float* x         = (const float*)d_in[0];
    const float* coords    = (const float*)d_in[1];
    const float* attn_bias = (const float*)d_in[2];
    const float* Wqkv      = (const float*)d_in[3];
    const float* bqkv      = (const float*)d_in[4];
    const float* rel_w     = (const float*)d_in[5];
    float* out = (float*)d_out;

    // 1. QKV projection
    qkv_gemm_kernel<<<dim3(TD_ / 128, M_ / 128), 256>>>(x, Wqkv, bqkv);

    // 2. coord projection
    coord_kernel<<<(B_ * H_ * N_ + 255) / 256, 256>>>(coords, rel_w);

    // 3. flash attention (dynamic smem 66048 B > 48 KB default -> opt in)
    const int smem_bytes = (64 * 64 + 64 * 65 + 64 * 64 + 64 * 65) * 4;
    cudaFuncSetAttribute(attn_kernel,
                         cudaFuncAttributeMaxDynamicSharedMemorySize,
                         smem_bytes);
    attn_kernel<<<dim3(N_ / 64, B_ * H_), 256, smem_bytes>>>(attn_bias, out);
}

// round 3
// speedup vs baseline: 1.1748x; 1.1748x over previous
#include <cuda_runtime.h>
#include <cuda_bf16.h>
#include <math.h>
#include <stdint.h>

#define B_  2
#define N_  2048
#define D_  1024
#define H_  16
#define HD_ 64
#define TD_ 3072          // 3*D
#define M_  4096          // B*N
#define KP_ 3072          // split-bf16 expanded K (3 * 1024)
#define NKT 96            // KP_/32 k-tiles

// ---------------- device scratch (globals: allocation-rule safe) -----------
__device__ float g_qkv[(size_t)M_ * TD_];            // 50 MB fp32 qkv
__device__ float g_cp [B_ * H_ * N_];                // coord_proj
__device__ uint4 g_A16[(size_t)M_  * KP_ / 8];       // bf16 A'  [m][k']
__device__ uint4 g_B16[(size_t)TD_ * KP_ / 8];       // bf16 B'^T [n][k']

// ---------------------------------------------------------------------------
// A' conversion: A'[m][k'] = [hi(x) | lo(x) | hi(x)] over k' thirds.
// thread = (m, 8-consecutive-k' group). Reads and writes fully coalesced.
// ---------------------------------------------------------------------------
__global__ __launch_bounds__(256)
void conv_a_kernel(const float* __restrict__ x)
{
    int idx = blockIdx.x * 256 + threadIdx.x;       // m*384 + g
    int m   = idx / 384;
    int g   = idx - m * 384;
    int kp0 = g * 8;
    int kk0 = kp0 & 1023;
    bool lo_region = (kp0 >= 1024) && (kp0 < 2048);

    float4 v0 = *(const float4*)(x + (size_t)m * 1024 + kk0);
    float4 v1 = *(const float4*)(x + (size_t)m * 1024 + kk0 + 4);
    float vv[8] = {v0.x, v0.y, v0.z, v0.w, v1.x, v1.y, v1.z, v1.w};

    __nv_bfloat16 o[8];
#pragma unroll
    for (int t = 0; t < 8; t++) {
        __nv_bfloat16 h = __float2bfloat16(vv[t]);
        if (lo_region) h = __float2bfloat16(vv[t] - __bfloat162float(h));
        o[t] = h;
    }
    g_A16[((size_t)m * KP_ + kp0) >> 3] = *(const uint4*)o;
}

// ---------------------------------------------------------------------------
// B' conversion: B'^T[n][k'] = [hi | hi | lo] of W[k mod 1024][n].
// warp = (kgroup g, 32 consecutive n). Reads coalesced (lane over n);
// writes 16B per lane.
// ---------------------------------------------------------------------------
__global__ __launch_bounds__(256)
void conv_b_kernel(const float* __restrict__ W)
{
    int wid  = threadIdx.x >> 5;
    int lane = threadIdx.x & 31;
    int gw   = blockIdx.x * 8 + wid;                // 0 .. 384*96-1
    int g    = gw / 96;                             // k-group (8 k' each)
    int n    = (gw - g * 96) * 32 + lane;
    int kp0  = g * 8;
    int kk0  = kp0 & 1023;
    bool lo_region = (kp0 >= 2048);

    __nv_bfloat16 o[8];
#pragma unroll
    for (int t = 0; t < 8; t++) {
        float w = __ldg(W + (size_t)(kk0 + t) * TD_ + n);
        __nv_bfloat16 h = __float2bfloat16(w);
        if (lo_region) h = __float2bfloat16(w - __bfloat162float(h));
        o[t] = h;
    }
    g_B16[((size_t)n * KP_ + kp0) >> 3] = *(const uint4*)o;
}

// ---------------------------------------------------------------------------
// QKV GEMM via mma.sync bf16: g_qkv[4096,3072] = A' @ B'^T + bias
// CTA 128x128, BK=32, 8 warps (4m x 2n), warp tile 32x64.
// smem stride 40 bf16 (20 words) -> conflict-free fragment LDS.
// ---------------------------------------------------------------------------
__device__ __forceinline__ void mma16816(float* c, const uint32_t* a,
                                         const uint32_t* b)
{
    asm volatile(
        "mma.sync.aligned.m16n8k16.row.col.f32.bf16.bf16.f32 "
        "{%0,%1,%2,%3}, {%4,%5,%6,%7}, {%8,%9}, {%0,%1,%2,%3};"
        : "+f"(c[0]), "+f"(c[1]), "+f"(c[2]), "+f"(c[3])
        : "r"(a[0]), "r"(a[1]), "r"(a[2]), "r"(a[3]), "r"(b[0]), "r"(b[1]));
}

__global__ __launch_bounds__(256)
void qkv_mma_kernel(const float* __restrict__ bias)
{
    __shared__ __nv_bfloat16 As[2][128][40];
    __shared__ __nv_bfloat16 Bs[2][128][40];

    const int tid  = threadIdx.x;
    const int wid  = tid >> 5;
    const int lane = tid & 31;
    const int grp  = lane >> 2;          // 0..7
    const int qp   = lane & 3;           // 0..3
    const int mb   = blockIdx.y;         // 32
    const int nb   = blockIdx.x;         // 24
    const int m0   = (wid >> 1) * 32;    // warp m offset in tile
    const int n0w  = (wid & 1) * 64;     // warp n offset in tile

    const uint4* gA = g_A16 + ((size_t)(mb * 128) * KP_ >> 3);
    const uint4* gB = g_B16 + ((size_t)(nb * 128) * KP_ >> 3);

    // loader mapping: 512 chunks of 16B per operand tile; 2 per thread
    const int lrow0 = tid >> 2;          // chunk p=0 row (0..63)
    const int lcg   = tid & 3;           // 16B group within 32-k row

    float acc[2][8][4];
#pragma unroll
    for (int mt = 0; mt < 2; mt++)
#pragma unroll
        for (int nt = 0; nt < 8; nt++)
#pragma unroll
            for (int i = 0; i < 4; i++) acc[mt][nt][i] = 0.f;

    // ---- prologue: load k-tile 0 into buffer 0 ----
#pragma unroll
    for (int p = 0; p < 2; p++) {
        int row = lrow0 + p * 64;
        *(uint4*)&As[0][row][lcg * 8] = gA[(size_t)row * (KP_ >> 3) + lcg];
        *(uint4*)&Bs[0][row][lcg * 8] = gB[(size_t)row * (KP_ >> 3) + lcg];
    }
    __syncthreads();

    for (int kt = 0; kt < NKT; kt++) {
        const int cur = kt & 1;

        // prefetch next k-tile into registers
        uint4 av[2], bv[2];
        if (kt + 1 < NKT) {
            int kq = (kt + 1) * 4;       // uint4 offset of k0
#pragma unroll
            for (int p = 0; p < 2; p++) {
                int row = lrow0 + p * 64;
                av[p] = gA[(size_t)row * (KP_ >> 3) + kq + lcg];
                bv[p] = gB[(size_t)row * (KP_ >> 3) + kq + lcg];
            }
        }

        // ---- compute on current buffer ----
#pragma unroll
        for (int ks = 0; ks < 2; ks++) {
            const int kc = ks * 16 + qp * 2;
            uint32_t a[2][4];
#pragma unroll
            for (int mt = 0; mt < 2; mt++) {
                int r = m0 + mt * 16 + grp;
                a[mt][0] = *(const uint32_t*)&As[cur][r][kc];
                a[mt][1] = *(const uint32_t*)&As[cur][r + 8][kc];
                a[mt][2] = *(const uint32_t*)&As[cur][r][kc + 8];
                a[mt][3] = *(const uint32_t*)&As[cur][r + 8][kc + 8];
            }
#pragma unroll
            for (int nt = 0; nt < 8; nt++) {
                int nr = n0w + nt * 8 + grp;
                uint32_t b[2];
                b[0] = *(const uint32_t*)&Bs[cur][nr][kc];
                b[1] = *(const uint32_t*)&Bs[cur][nr][kc + 8];
#pragma unroll
                for (int mt = 0; mt < 2; mt++)
                    mma16816(acc[mt][nt], a[mt], b);
            }
        }

        // ---- store prefetched tile, flip ----
        if (kt + 1 < NKT) {
#pragma unroll
            for (int p = 0; p < 2; p++) {
                int row = lrow0 + p * 64;
                *(uint4*)&As[cur ^ 1][row][lcg * 8] = av[p];
                *(uint4*)&Bs[cur ^ 1][row][lcg * 8] = bv[p];
            }
            __syncthreads();
        }
    }

    // ---- epilogue: write C + bias ----
#pragma unroll
    for (int mt = 0; mt < 2; mt++) {
        int row = mb * 128 + m0 + mt * 16 + grp;
#pragma unroll
        for (int nt = 0; nt < 8; nt++) {
            int col = nb * 128 + n0w + nt * 8 + qp * 2;
            float bx = __ldg(bias + col);
            float by = __ldg(bias + col + 1);
            float2 v0 = { acc[mt][nt][0] + bx, acc[mt][nt][1] + by };
            float2 v1 = { acc[mt][nt][2] + bx, acc[mt][nt][3] + by };
            *(float2*)&g_qkv[(size_t)row * TD_ + col] = v0;
            *(float2*)&g_qkv[(size_t)(row + 8) * TD_ + col] = v1;
        }
    }
}

// ---------------------------------------------------------------------------
// coord_proj[b,h,n] = coords[b,n,:] . rel_weight[h,:]   (CD = 3)
// ---------------------------------------------------------------------------
__global__ void coord_kernel(const float* __restrict__ coords,
                             const float* __restrict__ rw)
{
    int idx = blockIdx.x * blockDim.x + threadIdx.x;
    if (idx >= B_ * H_ * N_) return;
    int n = idx % N_;
    int h = (idx / N_) % H_;
    int b = idx / (N_ * H_);
    const float* c = coords + ((size_t)b * N_ + n) * 3;
    const float* w = rw + h * 3;
    g_cp[idx] = c[0] * w[0] + c[1] * w[1] + c[2] * w[2];
}

// ---------------------------------------------------------------------------
// Flash attention, fp32 (round-1 proven version, unchanged).
// ---------------------------------------------------------------------------
__global__ __launch_bounds__(256)
void attn_kernel(const float* __restrict__ bias2d, float* __restrict__ out)
{
    extern __shared__ float sm[];
    float (*Qs)[64] = (float (*)[64])(sm);
    float (*Ks)[65] = (float (*)[65])(sm + 4096);
    float (*Vs)[64] = (float (*)[64])(sm + 8256);
    float (*Ps)[65] = (float (*)[65])(sm + 12352);

    const int bh = blockIdx.y;
    const int b  = bh >> 4;
    const int h  = bh & 15;
    const int q0 = blockIdx.x * 64;
    const int tid = threadIdx.x;
    const int tr = tid >> 4;
    const int tc = tid & 15;

    const float* qbase = g_qkv + (size_t)(b * N_) * TD_ + h * HD_;
    const float* cpb   = g_cp + (size_t)bh * N_;

#pragma unroll
    for (int p = 0; p < 4; p++) {
        int idx = tid + p * 256;
        int row = idx >> 4;
        int c4  = (idx & 15) << 2;
        float4 v = *(const float4*)(qbase + (size_t)(q0 + row) * TD_ + c4);
        v.x *= 0.125f; v.y *= 0.125f; v.z *= 0.125f; v.w *= 0.125f;
        *(float4*)(&Qs[row][c4]) = v;
    }

    float O[4][4];
    float m[4], l[4];
#pragma unroll
    for (int i = 0; i < 4; i++) {
        m[i] = -1e30f; l[i] = 0.f;
#pragma unroll
        for (int x = 0; x < 4; x++) O[i][x] = 0.f;
    }

    for (int k0 = 0; k0 < N_; k0 += 64) {
        __syncthreads();
#pragma unroll
        for (int p = 0; p < 4; p++) {
            int idx = tid + p * 256;
            int row = idx >> 4;
            int c4  = (idx & 15) << 2;
            const float* src = qbase + (size_t)(k0 + row) * TD_;
            float4 kv = *(const float4*)(src + 1024 + c4);
            Ks[row][c4 + 0] = kv.x; Ks[row][c4 + 1] = kv.y;
            Ks[row][c4 + 2] = kv.z; Ks[row][c4 + 3] = kv.w;
            float4 vv = *(const float4*)(src + 2048 + c4);
            *(float4*)(&Vs[row][c4]) = vv;
        }
        __syncthreads();

        float S[4][4];
#pragma unroll
        for (int i = 0; i < 4; i++)
#pragma unroll
            for (int j = 0; j < 4; j++) S[i][j] = 0.f;

#pragma unroll 8
        for (int d = 0; d < 64; d++) {
            float ra[4], rb[4];
#pragma unroll
            for (int i = 0; i < 4; i++) ra[i] = Qs[tr * 4 + i][d];
#pragma unroll
            for (int j = 0; j < 4; j++) rb[j] = Ks[tc * 4 + j][d];
#pragma unroll
            for (int i = 0; i < 4; i++)
#pragma unroll
                for (int j = 0; j < 4; j++)
                    S[i][j] += ra[i] * rb[j];
        }

        float cpj[4];
#pragma unroll
        for (int j = 0; j < 4; j++) cpj[j] = __ldg(cpb + k0 + tc * 4 + j);
#pragma unroll
        for (int i = 0; i < 4; i++) {
            const float4 bv = *(const float4*)(bias2d +
                (size_t)(q0 + tr * 4 + i) * N_ + k0 + tc * 4);
            S[i][0] += bv.x - cpj[0];
            S[i][1] += bv.y - cpj[1];
            S[i][2] += bv.z - cpj[2];
            S[i][3] += bv.w - cpj[3];
        }

#pragma unroll
        for (int i = 0; i < 4; i++) {
            float mx = fmaxf(fmaxf(S[i][0], S[i][1]), fmaxf(S[i][2], S[i][3]));
#pragma unroll
            for (int s = 8; s >= 1; s >>= 1)
                mx = fmaxf(mx, __shfl_xor_sync(0xffffffffu, mx, s));
            float mn = fmaxf(m[i], mx);
            float alpha = __expf(m[i] - mn);
            m[i] = mn;
            float rs = 0.f;
#pragma unroll
            for (int j = 0; j < 4; j++) {
                S[i][j] = __expf(S[i][j] - mn);
                rs += S[i][j];
            }
#pragma unroll
            for (int s = 8; s >= 1; s >>= 1)
                rs += __shfl_xor_sync(0xffffffffu, rs, s);
            l[i] = l[i] * alpha + rs;
#pragma unroll
            for (int x = 0; x < 4; x++) O[i][x] *= alpha;
#pragma unroll
            for (int j = 0; j < 4; j++)
                Ps[tr * 4 + i][tc * 4 + j] = S[i][j];
        }
        __syncthreads();

#pragma unroll 4
        for (int j = 0; j < 64; j++) {
            float pa[4];
#pragma unroll
            for (int i = 0; i < 4; i++) pa[i] = Ps[tr * 4 + i][j];
            const float4 vb = *(const float4*)(&Vs[j][tc * 4]);
#pragma unroll
            for (int i = 0; i < 4; i++) {
                O[i][0] += pa[i] * vb.x;
                O[i][1] += pa[i] * vb.y;
                O[i][2] += pa[i] * vb.z;
                O[i][3] += pa[i] * vb.w;
            }
        }
    }

#pragma unroll
    for (int i = 0; i < 4; i++) {
        float inv = 1.0f / l[i];
        int q = q0 + tr * 4 + i;
        float4 ov;
        ov.x = O[i][0] * inv; ov.y = O[i][1] * inv;
        ov.z = O[i][2] * inv; ov.w = O[i][3] * inv;
        *(float4*)(&out[((size_t)(b * N_) + q) * D_ + h * HD_ + tc * 4]) = ov;
    }
}

// ---------------------------------------------------------------------------
extern "C" void kernel_launch(void* const* d_in, const int* in_sizes, int n_in,
                              void* d_out, int out_size)
{
    const float* x         = (const float*)d_in[0];
    const float* coords    = (const float*)d_in[1];
    const float* attn_bias = (const float*)d_in[2];
    const float* Wqkv      = (const float*)d_in[3];
    const float* bqkv      = (const float*)d_in[4];
    const float* rel_w     = (const float*)d_in[5];
    float* out = (float*)d_out;

    // 1. split-bf16 operand conversion
    conv_a_kernel<<<(M_ * 384) / 256, 256>>>(x);
    conv_b_kernel<<<(TD_ / 32) * NKT * 4 / 8, 256>>>(Wqkv);  // 4608 blocks

    // 2. QKV GEMM on tensor cores (mma.sync bf16, split-3)
    qkv_mma_kernel<<<dim3(TD_ / 128, M_ / 128), 256>>>(bqkv);

    // 3. coord projection
    coord_kernel<<<(B_ * H_ * N_ + 255) / 256, 256>>>(coords, rel_w);

    // 4. flash attention (fp32)
    const int attn_smem = (64 * 64 + 64 * 65 + 64 * 64 + 64 * 65) * 4;
    cudaFuncSetAttribute(attn_kernel,
                         cudaFuncAttributeMaxDynamicSharedMemorySize, attn_smem);
    attn_kernel<<<dim3(N_ / 64, B_ * H_), 256, attn_smem>>>(attn_bias, out);
}

// round 10
// speedup vs baseline: 1.8108x; 1.5413x over previous
#include <cuda_runtime.h>
#include <cuda_bf16.h>
#include <math.h>
#include <stdint.h>

#define B_  2
#define N_  2048
#define D_  1024
#define H_  16
#define HD_ 64
#define TD_ 3072          // 3*D
#define M_  4096          // B*N
#define KP_ 3072          // split-bf16 expanded K (3 * 1024)
#define NKT 96            // KP_/32 k-tiles

// ---------------- device scratch (globals: allocation-rule safe) -----------
__device__ float g_qkv[(size_t)M_ * TD_];            // 50 MB fp32 qkv
__device__ float g_cp [B_ * H_ * N_];                // coord_proj
__device__ uint4 g_A16[(size_t)M_  * KP_ / 8];       // bf16 A'  [m][k']
__device__ uint4 g_B16[(size_t)TD_ * KP_ / 8];       // bf16 B'^T [n][k']

// ---------------------------------------------------------------------------
__device__ __forceinline__ void mma16816(float* c, const uint32_t* a,
                                         const uint32_t* b)
{
    asm volatile(
        "mma.sync.aligned.m16n8k16.row.col.f32.bf16.bf16.f32 "
        "{%0,%1,%2,%3}, {%4,%5,%6,%7}, {%8,%9}, {%0,%1,%2,%3};"
        : "+f"(c[0]), "+f"(c[1]), "+f"(c[2]), "+f"(c[3])
        : "r"(a[0]), "r"(a[1]), "r"(a[2]), "r"(a[3]), "r"(b[0]), "r"(b[1]));
}
// pack two f32 -> bf16x2 (lo = first elem in low half)
__device__ __forceinline__ uint32_t packbf(float lo, float hi)
{
    uint32_t r;
    asm("cvt.rn.bf16x2.f32 %0, %1, %2;" : "=r"(r) : "f"(hi), "f"(lo));
    return r;
}
// Dekker split of a pair: hi word + residual-lo word
__device__ __forceinline__ void packsplit(float a, float b,
                                          uint32_t& hw, uint32_t& lw)
{
    uint32_t h = packbf(a, b);
    float ra = a - __uint_as_float(h << 16);
    float rb = b - __uint_as_float(h & 0xffff0000u);
    hw = h;
    lw = packbf(ra, rb);
}
// word permutation: fragment words (qp, qp+4) -> adjacent (2qp, 2qp+1)
__device__ __forceinline__ int permw(int p)
{
    int j = p & 7;
    return (p >> 3) * 8 + (((j & 3) << 1) | (j >> 2));
}

// ---------------------------------------------------------------------------
// A' conversion (unchanged, proven)
// ---------------------------------------------------------------------------
__global__ __launch_bounds__(256)
void conv_a_kernel(const float* __restrict__ x)
{
    int idx = blockIdx.x * 256 + threadIdx.x;
    int m   = idx / 384;
    int g   = idx - m * 384;
    int kp0 = g * 8;
    int kk0 = kp0 & 1023;
    bool lo_region = (kp0 >= 1024) && (kp0 < 2048);

    float4 v0 = *(const float4*)(x + (size_t)m * 1024 + kk0);
    float4 v1 = *(const float4*)(x + (size_t)m * 1024 + kk0 + 4);
    float vv[8] = {v0.x, v0.y, v0.z, v0.w, v1.x, v1.y, v1.z, v1.w};

    __nv_bfloat16 o[8];
#pragma unroll
    for (int t = 0; t < 8; t++) {
        __nv_bfloat16 h = __float2bfloat16(vv[t]);
        if (lo_region) h = __float2bfloat16(vv[t] - __bfloat162float(h));
        o[t] = h;
    }
    g_A16[((size_t)m * KP_ + kp0) >> 3] = *(const uint4*)o;
}

__global__ __launch_bounds__(256)
void conv_b_kernel(const float* __restrict__ W)
{
    int wid  = threadIdx.x >> 5;
    int lane = threadIdx.x & 31;
    int gw   = blockIdx.x * 8 + wid;
    int g    = gw / 96;
    int n    = (gw - g * 96) * 32 + lane;
    int kp0  = g * 8;
    int kk0  = kp0 & 1023;
    bool lo_region = (kp0 >= 2048);

    __nv_bfloat16 o[8];
#pragma unroll
    for (int t = 0; t < 8; t++) {
        float w = __ldg(W + (size_t)(kk0 + t) * TD_ + n);
        __nv_bfloat16 h = __float2bfloat16(w);
        if (lo_region) h = __float2bfloat16(w - __bfloat162float(h));
        o[t] = h;
    }
    g_B16[((size_t)n * KP_ + kp0) >> 3] = *(const uint4*)o;
}

// ---------------------------------------------------------------------------
// QKV GEMM via mma.sync (unchanged, proven)
// ---------------------------------------------------------------------------
__global__ __launch_bounds__(256)
void qkv_mma_kernel(const float* __restrict__ bias)
{
    __shared__ __nv_bfloat16 As[2][128][40];
    __shared__ __nv_bfloat16 Bs[2][128][40];

    const int tid  = threadIdx.x;
    const int wid  = tid >> 5;
    const int lane = tid & 31;
    const int grp  = lane >> 2;
    const int qp   = lane & 3;
    const int mb   = blockIdx.y;
    const int nb   = blockIdx.x;
    const int m0   = (wid >> 1) * 32;
    const int n0w  = (wid & 1) * 64;

    const uint4* gA = g_A16 + ((size_t)(mb * 128) * KP_ >> 3);
    const uint4* gB = g_B16 + ((size_t)(nb * 128) * KP_ >> 3);

    const int lrow0 = tid >> 2;
    const int lcg   = tid & 3;

    float acc[2][8][4];
#pragma unroll
    for (int mt = 0; mt < 2; mt++)
#pragma unroll
        for (int nt = 0; nt < 8; nt++)
#pragma unroll
            for (int i = 0; i < 4; i++) acc[mt][nt][i] = 0.f;

#pragma unroll
    for (int p = 0; p < 2; p++) {
        int row = lrow0 + p * 64;
        *(uint4*)&As[0][row][lcg * 8] = gA[(size_t)row * (KP_ >> 3) + lcg];
        *(uint4*)&Bs[0][row][lcg * 8] = gB[(size_t)row * (KP_ >> 3) + lcg];
    }
    __syncthreads();

    for (int kt = 0; kt < NKT; kt++) {
        const int cur = kt & 1;
        uint4 av[2], bv[2];
        if (kt + 1 < NKT) {
            int kq = (kt + 1) * 4;
#pragma unroll
            for (int p = 0; p < 2; p++) {
                int row = lrow0 + p * 64;
                av[p] = gA[(size_t)row * (KP_ >> 3) + kq + lcg];
                bv[p] = gB[(size_t)row * (KP_ >> 3) + kq + lcg];
            }
        }
#pragma unroll
        for (int ks = 0; ks < 2; ks++) {
            const int kc = ks * 16 + qp * 2;
            uint32_t a[2][4];
#pragma unroll
            for (int mt = 0; mt < 2; mt++) {
                int r = m0 + mt * 16 + grp;
                a[mt][0] = *(const uint32_t*)&As[cur][r][kc];
                a[mt][1] = *(const uint32_t*)&As[cur][r + 8][kc];
                a[mt][2] = *(const uint32_t*)&As[cur][r][kc + 8];
                a[mt][3] = *(const uint32_t*)&As[cur][r + 8][kc + 8];
            }
#pragma unroll
            for (int nt = 0; nt < 8; nt++) {
                int nr = n0w + nt * 8 + grp;
                uint32_t b[2];
                b[0] = *(const uint32_t*)&Bs[cur][nr][kc];
                b[1] = *(const uint32_t*)&Bs[cur][nr][kc + 8];
#pragma unroll
                for (int mt = 0; mt < 2; mt++)
                    mma16816(acc[mt][nt], a[mt], b);
            }
        }
        if (kt + 1 < NKT) {
#pragma unroll
            for (int p = 0; p < 2; p++) {
                int row = lrow0 + p * 64;
                *(uint4*)&As[cur ^ 1][row][lcg * 8] = av[p];
                *(uint4*)&Bs[cur ^ 1][row][lcg * 8] = bv[p];
            }
            __syncthreads();
        }
    }

#pragma unroll
    for (int mt = 0; mt < 2; mt++) {
        int row = mb * 128 + m0 + mt * 16 + grp;
#pragma unroll
        for (int nt = 0; nt < 8; nt++) {
            int col = nb * 128 + n0w + nt * 8 + qp * 2;
            float bx = __ldg(bias + col);
            float by = __ldg(bias + col + 1);
            float2 v0 = { acc[mt][nt][0] + bx, acc[mt][nt][1] + by };
            float2 v1 = { acc[mt][nt][2] + bx, acc[mt][nt][3] + by };
            *(float2*)&g_qkv[(size_t)row * TD_ + col] = v0;
            *(float2*)&g_qkv[(size_t)(row + 8) * TD_ + col] = v1;
        }
    }
}

// ---------------------------------------------------------------------------
__global__ void coord_kernel(const float* __restrict__ coords,
                             const float* __restrict__ rw)
{
    int idx = blockIdx.x * blockDim.x + threadIdx.x;
    if (idx >= B_ * H_ * N_) return;
    int n = idx % N_;
    int h = (idx / N_) % H_;
    int b = idx / (N_ * H_);
    const float* c = coords + ((size_t)b * N_ + n) * 3;
    const float* w = rw + h * 3;
    g_cp[idx] = c[0] * w[0] + c[1] * w[1] + c[2] * w[2];
}

// ---------------------------------------------------------------------------
// Flash attention on tensor cores. 64 q-rows/CTA, 4 warps, k-tiles of 64.
// smem words: QS[64][72] | KS[64][72] | VT[64][73] | VF(fp32)[64][68]
// hi region = words 0..31 (k-pairs, permuted), lo region = +32.
// NOTE: VT row stride 73 is ODD -> VT reads must be 32-bit (no LDS.64).
// ---------------------------------------------------------------------------
#define QS_OFF 0
#define KS_OFF 4608
#define VT_OFF 9216
#define VF_OFF 13888
#define AT_SMEM_WORDS (VF_OFF + 64 * 68)   // 18240 words = 72960 B

__global__ __launch_bounds__(128)
void attn_tc_kernel(const float* __restrict__ bias2d, float* __restrict__ out)
{
    extern __shared__ uint32_t smw[];
    uint32_t* QS = smw + QS_OFF;
    uint32_t* KS = smw + KS_OFF;
    uint32_t* VT = smw + VT_OFF;
    float*    VF = (float*)(smw + VF_OFF);

    const int tid  = threadIdx.x;
    const int wid  = tid >> 5;
    const int lane = tid & 31;
    const int grp  = lane >> 2;
    const int qp   = lane & 3;
    const int bh   = blockIdx.y;
    const int b    = bh >> 4;
    const int h    = bh & 15;
    const int q0   = blockIdx.x * 64;

    const float* hb  = g_qkv + (size_t)(b * N_) * TD_ + h * HD_;
    const float* cpb = g_cp + (size_t)bh * N_;

    // ---- load Q tile once: scale 0.125, split hi/lo, pack pairs ----
#pragma unroll
    for (int p = 0; p < 8; p++) {
        int idx = p * 128 + tid;
        int row = idx >> 4;
        int c4  = (idx & 15) << 2;
        float4 v = *(const float4*)(hb + (size_t)(q0 + row) * TD_ + c4);
        v.x *= 0.125f; v.y *= 0.125f; v.z *= 0.125f; v.w *= 0.125f;
        uint32_t h0, l0, h1, l1;
        packsplit(v.x, v.y, h0, l0);
        packsplit(v.z, v.w, h1, l1);
        int p0 = c4 >> 1;
        uint32_t* r = QS + row * 72;
        r[permw(p0)]          = h0;
        r[permw(p0 + 1)]      = h1;
        r[32 + permw(p0)]     = l0;
        r[32 + permw(p0 + 1)] = l1;
    }

    float Oacc[8][4];
#pragma unroll
    for (int nt = 0; nt < 8; nt++)
#pragma unroll
        for (int i = 0; i < 4; i++) Oacc[nt][i] = 0.f;
    float m0 = -1e30f, m1 = -1e30f, l0s = 0.f, l1s = 0.f;

    const float* brow0 = bias2d + (size_t)(q0 + 16 * wid + grp) * N_;
    const float* brow1 = brow0 + 8 * N_;

    for (int k0 = 0; k0 < N_; k0 += 64) {
        __syncthreads();
        // ---- load K (split+pack) and V (fp32 staged, xor-swizzled) ----
#pragma unroll
        for (int p = 0; p < 8; p++) {
            int idx = p * 128 + tid;
            int row = idx >> 4;
            int c4  = (idx & 15) << 2;
            const float* src = hb + (size_t)(k0 + row) * TD_ + c4;
            float4 kv = *(const float4*)(src + 1024);
            uint32_t h0, l0, h1, l1;
            packsplit(kv.x, kv.y, h0, l0);
            packsplit(kv.z, kv.w, h1, l1);
            int p0 = c4 >> 1;
            uint32_t* r = KS + row * 72;
            r[permw(p0)]          = h0;
            r[permw(p0 + 1)]      = h1;
            r[32 + permw(p0)]     = l0;
            r[32 + permw(p0 + 1)] = l1;
            float4 vv = *(const float4*)(src + 2048);
            *(float4*)&VF[row * 68 + ((((c4 >> 2) ^ (row & 15))) << 2)] = vv;
        }
        __syncthreads();

        // ---- transpose V: VF[k][d] -> VT[d][k-pairs hi|lo] ----
        {
            int d  = tid & 63;
            int kh = tid >> 6;
#pragma unroll
            for (int i = 0; i < 16; i++) {
                int k  = kh * 32 + 2 * i;
                float f0 = VF[k * 68 + ((((d >> 2) ^ (k & 15))) << 2) + (d & 3)];
                float f1 = VF[(k + 1) * 68 + ((((d >> 2) ^ ((k + 1) & 15))) << 2) + (d & 3)];
                uint32_t hw, lw;
                packsplit(f0, f1, hw, lw);
                int pi = kh * 16 + i;
                VT[d * 73 + permw(pi)]      = hw;
                VT[d * 73 + 32 + permw(pi)] = lw;
            }
        }

        // ---- S = Q'K'^T via mma (3-term split) ----
        float S[8][4];
#pragma unroll
        for (int nt = 0; nt < 8; nt++)
#pragma unroll
            for (int i = 0; i < 4; i++) S[nt][i] = 0.f;

#pragma unroll
        for (int ck = 0; ck < 4; ck++) {
            const uint32_t* q0p = QS + (16 * wid + grp) * 72 + 8 * ck + 2 * qp;
            const uint32_t* q1p = QS + (16 * wid + grp + 8) * 72 + 8 * ck + 2 * qp;
            uint2 hA = *(const uint2*)q0p;
            uint2 hB = *(const uint2*)q1p;
            uint2 lA = *(const uint2*)(q0p + 32);
            uint2 lB = *(const uint2*)(q1p + 32);
            uint32_t ah[4] = {hA.x, hB.x, hA.y, hB.y};
            uint32_t al[4] = {lA.x, lB.x, lA.y, lB.y};
#pragma unroll
            for (int nt = 0; nt < 8; nt++) {
                uint2 bv = *(const uint2*)(KS + (8 * nt + grp) * 72 + 8 * ck + 2 * qp);
                uint32_t bb[2] = {bv.x, bv.y};
                mma16816(S[nt], ah, bb);
                mma16816(S[nt], al, bb);
            }
        }
#pragma unroll
        for (int ck = 0; ck < 4; ck++) {
            const uint32_t* q0p = QS + (16 * wid + grp) * 72 + 8 * ck + 2 * qp;
            const uint32_t* q1p = QS + (16 * wid + grp + 8) * 72 + 8 * ck + 2 * qp;
            uint2 hA = *(const uint2*)q0p;
            uint2 hB = *(const uint2*)q1p;
            uint32_t ah[4] = {hA.x, hB.x, hA.y, hB.y};
#pragma unroll
            for (int nt = 0; nt < 8; nt++) {
                uint2 bv = *(const uint2*)(KS + (8 * nt + grp) * 72 + 32 + 8 * ck + 2 * qp);
                uint32_t bb[2] = {bv.x, bv.y};
                mma16816(S[nt], ah, bb);
            }
        }

        // ---- add bias[q,k] - cp[k] ----
#pragma unroll
        for (int nt = 0; nt < 8; nt++) {
            int col = k0 + 8 * nt + 2 * qp;
            float2 cpv = *(const float2*)(cpb + col);
            float2 b0 = *(const float2*)(brow0 + col);
            float2 b1 = *(const float2*)(brow1 + col);
            S[nt][0] += b0.x - cpv.x;
            S[nt][1] += b0.y - cpv.y;
            S[nt][2] += b1.x - cpv.x;
            S[nt][3] += b1.y - cpv.y;
        }

        // ---- online softmax (rows grp, grp+8; quad shuffles over qp) ----
        float mx0 = -1e30f, mx1 = -1e30f;
#pragma unroll
        for (int nt = 0; nt < 8; nt++) {
            mx0 = fmaxf(mx0, fmaxf(S[nt][0], S[nt][1]));
            mx1 = fmaxf(mx1, fmaxf(S[nt][2], S[nt][3]));
        }
        mx0 = fmaxf(mx0, __shfl_xor_sync(0xffffffffu, mx0, 1));
        mx0 = fmaxf(mx0, __shfl_xor_sync(0xffffffffu, mx0, 2));
        mx1 = fmaxf(mx1, __shfl_xor_sync(0xffffffffu, mx1, 1));
        mx1 = fmaxf(mx1, __shfl_xor_sync(0xffffffffu, mx1, 2));
        float mn0 = fmaxf(m0, mx0);
        float mn1 = fmaxf(m1, mx1);
        float a0 = __expf(m0 - mn0);
        float a1 = __expf(m1 - mn1);
        m0 = mn0; m1 = mn1;
        float rs0 = 0.f, rs1 = 0.f;
#pragma unroll
        for (int nt = 0; nt < 8; nt++) {
            S[nt][0] = __expf(S[nt][0] - mn0);
            S[nt][1] = __expf(S[nt][1] - mn0);
            S[nt][2] = __expf(S[nt][2] - mn1);
            S[nt][3] = __expf(S[nt][3] - mn1);
            rs0 += S[nt][0] + S[nt][1];
            rs1 += S[nt][2] + S[nt][3];
        }
        rs0 += __shfl_xor_sync(0xffffffffu, rs0, 1);
        rs0 += __shfl_xor_sync(0xffffffffu, rs0, 2);
        rs1 += __shfl_xor_sync(0xffffffffu, rs1, 1);
        rs1 += __shfl_xor_sync(0xffffffffu, rs1, 2);
        l0s = l0s * a0 + rs0;
        l1s = l1s * a1 + rs1;
#pragma unroll
        for (int nt = 0; nt < 8; nt++) {
            Oacc[nt][0] *= a0; Oacc[nt][1] *= a0;
            Oacc[nt][2] *= a1; Oacc[nt][3] *= a1;
        }

        // ---- pack P fragments (hi + residual lo) ----
        uint32_t Ph[4][4], Pl[4][4];
#pragma unroll
        for (int ck = 0; ck < 4; ck++) {
            int u = 2 * ck, v = u + 1;
            packsplit(S[u][0], S[u][1], Ph[ck][0], Pl[ck][0]);
            packsplit(S[u][2], S[u][3], Ph[ck][1], Pl[ck][1]);
            packsplit(S[v][0], S[v][1], Ph[ck][2], Pl[ck][2]);
            packsplit(S[v][2], S[v][3], Ph[ck][3], Pl[ck][3]);
        }

        __syncthreads();   // VT complete across warps before PV

        // ---- O += P'V' (3-term split) ----
        // VT stride 73 (odd) -> scalar 32-bit loads only (8B alignment
        // not guaranteed; this was the source of the misaligned-address
        // fault in round 8).
#pragma unroll
        for (int ck = 0; ck < 4; ck++) {
#pragma unroll
            for (int nt = 0; nt < 8; nt++) {
                const uint32_t* vp = VT + (8 * nt + grp) * 73 + 8 * ck + 2 * qp;
                uint32_t bb[2] = { vp[0], vp[1] };
                mma16816(Oacc[nt], Ph[ck], bb);
                mma16816(Oacc[nt], Pl[ck], bb);
            }
        }
#pragma unroll
        for (int ck = 0; ck < 4; ck++) {
#pragma unroll
            for (int nt = 0; nt < 8; nt++) {
                const uint32_t* vp = VT + (8 * nt + grp) * 73 + 32 + 8 * ck + 2 * qp;
                uint32_t bb[2] = { vp[0], vp[1] };
                mma16816(Oacc[nt], Ph[ck], bb);
            }
        }
    }

    // ---- epilogue ----
    float inv0 = 1.0f / l0s, inv1 = 1.0f / l1s;
    float* or0 = out + (size_t)(b * N_ + q0 + 16 * wid + grp) * D_ + h * HD_;
    float* or1 = or0 + 8 * D_;
#pragma unroll
    for (int nt = 0; nt < 8; nt++) {
        int c = 8 * nt + 2 * qp;
        float2 v0 = { Oacc[nt][0] * inv0, Oacc[nt][1] * inv0 };
        float2 v1 = { Oacc[nt][2] * inv1, Oacc[nt][3] * inv1 };
        *(float2*)(or0 + c) = v0;
        *(float2*)(or1 + c) = v1;
    }
}

// ---------------------------------------------------------------------------
extern "C" void kernel_launch(void* const* d_in, const int* in_sizes, int n_in,
                              void* d_out, int out_size)
{
    const float* x         = (const float*)d_in[0];
    const float* coords    = (const float*)d_in[1];
    const float* attn_bias = (const float*)d_in[2];
    const float* Wqkv      = (const float*)d_in[3];
    const float* bqkv      = (const float*)d_in[4];
    const float* rel_w     = (const float*)d_in[5];
    float* out = (float*)d_out;

    conv_a_kernel<<<(M_ * 384) / 256, 256>>>(x);
    conv_b_kernel<<<(TD_ / 32) * NKT * 4 / 8, 256>>>(Wqkv);

    qkv_mma_kernel<<<dim3(TD_ / 128, M_ / 128), 256>>>(bqkv);

    coord_kernel<<<(B_ * H_ * N_ + 255) / 256, 256>>>(coords, rel_w);

    const int attn_smem = AT_SMEM_WORDS * 4;   // 72960 B
    cudaFuncSetAttribute(attn_tc_kernel,
                         cudaFuncAttributeMaxDynamicSharedMemorySize, attn_smem);
    attn_tc_kernel<<<dim3(N_ / 64, B_ * H_), 128, attn_smem>>>(attn_bias, out);
}

// round 12
// speedup vs baseline: 2.1373x; 1.1803x over previous
#include <cuda_runtime.h>
#include <cuda_bf16.h>
#include <math.h>
#include <stdint.h>

#define B_  2
#define N_  2048
#define D_  1024
#define H_  16
#define HD_ 64
#define TD_ 3072          // 3*D
#define M_  4096          // B*N
#define KP_ 3072          // split-bf16 expanded K (3 * 1024)
#define NKT 96            // KP_/32 k-tiles

// ---------------- device scratch (globals: allocation-rule safe) -----------
__device__ float g_qkv[(size_t)M_ * TD_];            // 50 MB fp32 qkv
__device__ float g_cp [B_ * H_ * N_];                // coord_proj
__device__ uint4 g_A16[(size_t)M_  * KP_ / 8];       // bf16 A'  [m][k']
__device__ uint4 g_B16[(size_t)TD_ * KP_ / 8];       // bf16 B'^T [n][k']
__device__ uint32_t g_Kp[(size_t)32 * 2048 * 64];    // 16 MB packed K' [bh][n][64w]
__device__ uint32_t g_Vt[(size_t)32 * 32 * 64 * 64]; // 16 MB packed V'^T [bh][kt][d][64w]

// ---------------------------------------------------------------------------
__device__ __forceinline__ void mma16816(float* c, const uint32_t* a,
                                         const uint32_t* b)
{
    asm volatile(
        "mma.sync.aligned.m16n8k16.row.col.f32.bf16.bf16.f32 "
        "{%0,%1,%2,%3}, {%4,%5,%6,%7}, {%8,%9}, {%0,%1,%2,%3};"
        : "+f"(c[0]), "+f"(c[1]), "+f"(c[2]), "+f"(c[3])
        : "r"(a[0]), "r"(a[1]), "r"(a[2]), "r"(a[3]), "r"(b[0]), "r"(b[1]));
}
// pack two f32 -> bf16x2 (lo = first elem in low half)
__device__ __forceinline__ uint32_t packbf(float lo, float hi)
{
    uint32_t r;
    asm("cvt.rn.bf16x2.f32 %0, %1, %2;" : "=r"(r) : "f"(hi), "f"(lo));
    return r;
}
// Dekker split of a pair: hi word + residual-lo word
__device__ __forceinline__ void packsplit(float a, float b,
                                          uint32_t& hw, uint32_t& lw)
{
    uint32_t h = packbf(a, b);
    float ra = a - __uint_as_float(h << 16);
    float rb = b - __uint_as_float(h & 0xffff0000u);
    hw = h;
    lw = packbf(ra, rb);
}
// word permutation: fragment words (qp, qp+4) -> adjacent (2qp, 2qp+1)
__device__ __forceinline__ int permw(int p)
{
    int j = p & 7;
    return (p >> 3) * 8 + (((j & 3) << 1) | (j >> 2));
}

// ---------------------------------------------------------------------------
// A' conversion (unchanged, proven)
// ---------------------------------------------------------------------------
__global__ __launch_bounds__(256)
void conv_a_kernel(const float* __restrict__ x)
{
    int idx = blockIdx.x * 256 + threadIdx.x;
    int m   = idx / 384;
    int g   = idx - m * 384;
    int kp0 = g * 8;
    int kk0 = kp0 & 1023;
    bool lo_region = (kp0 >= 1024) && (kp0 < 2048);

    float4 v0 = *(const float4*)(x + (size_t)m * 1024 + kk0);
    float4 v1 = *(const float4*)(x + (size_t)m * 1024 + kk0 + 4);
    float vv[8] = {v0.x, v0.y, v0.z, v0.w, v1.x, v1.y, v1.z, v1.w};

    __nv_bfloat16 o[8];
#pragma unroll
    for (int t = 0; t < 8; t++) {
        __nv_bfloat16 h = __float2bfloat16(vv[t]);
        if (lo_region) h = __float2bfloat16(vv[t] - __bfloat162float(h));
        o[t] = h;
    }
    g_A16[((size_t)m * KP_ + kp0) >> 3] = *(const uint4*)o;
}

__global__ __launch_bounds__(256)
void conv_b_kernel(const float* __restrict__ W)
{
    int wid  = threadIdx.x >> 5;
    int lane = threadIdx.x & 31;
    int gw   = blockIdx.x * 8 + wid;
    int g    = gw / 96;
    int n    = (gw - g * 96) * 32 + lane;
    int kp0  = g * 8;
    int kk0  = kp0 & 1023;
    bool lo_region = (kp0 >= 2048);

    __nv_bfloat16 o[8];
#pragma unroll
    for (int t = 0; t < 8; t++) {
        float w = __ldg(W + (size_t)(kk0 + t) * TD_ + n);
        __nv_bfloat16 h = __float2bfloat16(w);
        if (lo_region) h = __float2bfloat16(w - __bfloat162float(h));
        o[t] = h;
    }
    g_B16[((size_t)n * KP_ + kp0) >> 3] = *(const uint4*)o;
}

// ---------------------------------------------------------------------------
// QKV GEMM via mma.sync (unchanged, proven)
// ---------------------------------------------------------------------------
__global__ __launch_bounds__(256)
void qkv_mma_kernel(const float* __restrict__ bias)
{
    __shared__ __nv_bfloat16 As[2][128][40];
    __shared__ __nv_bfloat16 Bs[2][128][40];

    const int tid  = threadIdx.x;
    const int wid  = tid >> 5;
    const int lane = tid & 31;
    const int grp  = lane >> 2;
    const int qp   = lane & 3;
    const int mb   = blockIdx.y;
    const int nb   = blockIdx.x;
    const int m0   = (wid >> 1) * 32;
    const int n0w  = (wid & 1) * 64;

    const uint4* gA = g_A16 + ((size_t)(mb * 128) * KP_ >> 3);
    const uint4* gB = g_B16 + ((size_t)(nb * 128) * KP_ >> 3);

    const int lrow0 = tid >> 2;
    const int lcg   = tid & 3;

    float acc[2][8][4];
#pragma unroll
    for (int mt = 0; mt < 2; mt++)
#pragma unroll
        for (int nt = 0; nt < 8; nt++)
#pragma unroll
            for (int i = 0; i < 4; i++) acc[mt][nt][i] = 0.f;

#pragma unroll
    for (int p = 0; p < 2; p++) {
        int row = lrow0 + p * 64;
        *(uint4*)&As[0][row][lcg * 8] = gA[(size_t)row * (KP_ >> 3) + lcg];
        *(uint4*)&Bs[0][row][lcg * 8] = gB[(size_t)row * (KP_ >> 3) + lcg];
    }
    __syncthreads();

    for (int kt = 0; kt < NKT; kt++) {
        const int cur = kt & 1;
        uint4 av[2], bv[2];
        if (kt + 1 < NKT) {
            int kq = (kt + 1) * 4;
#pragma unroll
            for (int p = 0; p < 2; p++) {
                int row = lrow0 + p * 64;
                av[p] = gA[(size_t)row * (KP_ >> 3) + kq + lcg];
                bv[p] = gB[(size_t)row * (KP_ >> 3) + kq + lcg];
            }
        }
#pragma unroll
        for (int ks = 0; ks < 2; ks++) {
            const int kc = ks * 16 + qp * 2;
            uint32_t a[2][4];
#pragma unroll
            for (int mt = 0; mt < 2; mt++) {
                int r = m0 + mt * 16 + grp;
                a[mt][0] = *(const uint32_t*)&As[cur][r][kc];
                a[mt][1] = *(const uint32_t*)&As[cur][r + 8][kc];
                a[mt][2] = *(const uint32_t*)&As[cur][r][kc + 8];
                a[mt][3] = *(const uint32_t*)&As[cur][r + 8][kc + 8];
            }
#pragma unroll
            for (int nt = 0; nt < 8; nt++) {
                int nr = n0w + nt * 8 + grp;
                uint32_t b[2];
                b[0] = *(const uint32_t*)&Bs[cur][nr][kc];
                b[1] = *(const uint32_t*)&Bs[cur][nr][kc + 8];
#pragma unroll
                for (int mt = 0; mt < 2; mt++)
                    mma16816(acc[mt][nt], a[mt], b);
            }
        }
        if (kt + 1 < NKT) {
#pragma unroll
            for (int p = 0; p < 2; p++) {
                int row = lrow0 + p * 64;
                *(uint4*)&As[cur ^ 1][row][lcg * 8] = av[p];
                *(uint4*)&Bs[cur ^ 1][row][lcg * 8] = bv[p];
            }
            __syncthreads();
        }
    }

#pragma unroll
    for (int mt = 0; mt < 2; mt++) {
        int row = mb * 128 + m0 + mt * 16 + grp;
#pragma unroll
        for (int nt = 0; nt < 8; nt++) {
            int col = nb * 128 + n0w + nt * 8 + qp * 2;
            float bx = __ldg(bias + col);
            float by = __ldg(bias + col + 1);
            float2 v0 = { acc[mt][nt][0] + bx, acc[mt][nt][1] + by };
            float2 v1 = { acc[mt][nt][2] + bx, acc[mt][nt][3] + by };
            *(float2*)&g_qkv[(size_t)row * TD_ + col] = v0;
            *(float2*)&g_qkv[(size_t)(row + 8) * TD_ + col] = v1;
        }
    }
}

// ---------------------------------------------------------------------------
__global__ void coord_kernel(const float* __restrict__ coords,
                             const float* __restrict__ rw)
{
    int idx = blockIdx.x * blockDim.x + threadIdx.x;
    if (idx >= B_ * H_ * N_) return;
    int n = idx % N_;
    int h = (idx / N_) % H_;
    int b = idx / (N_ * H_);
    const float* c = coords + ((size_t)b * N_ + n) * 3;
    const float* w = rw + h * 3;
    g_cp[idx] = c[0] * w[0] + c[1] * w[1] + c[2] * w[2];
}

// ---------------------------------------------------------------------------
// K/V pre-conversion: per (bh, k-tile of 64) convert once.
//   g_Kp[bh][n][64w]       : K split-packed, permuted (hi 0..31, lo 32..63)
//   g_Vt[bh][kt][d][64w]   : V transposed + split-packed, permuted
// ---------------------------------------------------------------------------
__global__ __launch_bounds__(128)
void conv_kv_kernel()
{
    __shared__ float VF[64 * 68];

    const int kt  = blockIdx.x;          // 32
    const int bh  = blockIdx.y;          // 32
    const int b   = bh >> 4;
    const int h   = bh & 15;
    const int tid = threadIdx.x;
    const int k0  = kt * 64;

    const float* hb = g_qkv + (size_t)(b * N_) * TD_ + h * HD_;
    uint32_t* Kp = g_Kp + ((size_t)bh * 2048 + k0) * 64;

#pragma unroll
    for (int p = 0; p < 8; p++) {
        int idx = p * 128 + tid;
        int row = idx >> 4;
        int c4  = (idx & 15) << 2;
        const float* src = hb + (size_t)(k0 + row) * TD_ + c4;
        float4 kv = *(const float4*)(src + 1024);
        uint32_t h0, l0, h1, l1;
        packsplit(kv.x, kv.y, h0, l0);
        packsplit(kv.z, kv.w, h1, l1);
        int p0 = c4 >> 1;
        uint32_t* r = Kp + row * 64;
        r[permw(p0)]          = h0;
        r[permw(p0 + 1)]      = h1;
        r[32 + permw(p0)]     = l0;
        r[32 + permw(p0 + 1)] = l1;
        float4 vv = *(const float4*)(src + 2048);
        *(float4*)&VF[row * 68 + ((((c4 >> 2) ^ (row & 15))) << 2)] = vv;
    }
    __syncthreads();

    // transpose V: VF[k][d] -> g_Vt[bh][kt][d][words]
    {
        int d  = tid & 63;
        int kh = tid >> 6;
        uint32_t* Vt = g_Vt + (((size_t)bh * 32 + kt) * 64 + d) * 64;
#pragma unroll
        for (int i = 0; i < 16; i++) {
            int k = kh * 32 + 2 * i;
            float f0 = VF[k * 68 + ((((d >> 2) ^ (k & 15))) << 2) + (d & 3)];
            float f1 = VF[(k + 1) * 68 + ((((d >> 2) ^ ((k + 1) & 15))) << 2) + (d & 3)];
            uint32_t hw, lw;
            packsplit(f0, f1, hw, lw);
            int pi = kh * 16 + i;
            Vt[permw(pi)]      = hw;
            Vt[32 + permw(pi)] = lw;
        }
    }
}

// ---------------------------------------------------------------------------
// Flash attention on tensor cores. 64 q-rows/CTA, 4 warps, k-tiles of 64.
// smem words: QS[64][72] | KS[64][72] | VT[64][72]  (all even strides)
// hi region = words 0..31 (k-pairs, permuted), lo region = +32.
// K/V arrive pre-converted from g_Kp / g_Vt -> inner loop is pure copies+mma.
// ---------------------------------------------------------------------------
#define QS_OFF 0
#define KS_OFF 4608
#define VT_OFF 9216
#define AT_SMEM_WORDS (VT_OFF + 64 * 72)   // 13824 words = 55296 B

__global__ __launch_bounds__(128)
void attn_tc_kernel(const float* __restrict__ bias2d, float* __restrict__ out)
{
    extern __shared__ uint32_t smw[];
    uint32_t* QS = smw + QS_OFF;
    uint32_t* KS = smw + KS_OFF;
    uint32_t* VT = smw + VT_OFF;

    const int tid  = threadIdx.x;
    const int wid  = tid >> 5;
    const int lane = tid & 31;
    const int grp  = lane >> 2;
    const int qp   = lane & 3;
    const int bh   = blockIdx.y;
    const int b    = bh >> 4;
    const int h    = bh & 15;
    const int q0   = blockIdx.x * 64;

    const float* hb  = g_qkv + (size_t)(b * N_) * TD_ + h * HD_;
    const float* cpb = g_cp + (size_t)bh * N_;

    // ---- load Q tile once: scale 0.125, split hi/lo, pack pairs ----
#pragma unroll
    for (int p = 0; p < 8; p++) {
        int idx = p * 128 + tid;
        int row = idx >> 4;
        int c4  = (idx & 15) << 2;
        float4 v = *(const float4*)(hb + (size_t)(q0 + row) * TD_ + c4);
        v.x *= 0.125f; v.y *= 0.125f; v.z *= 0.125f; v.w *= 0.125f;
        uint32_t h0, l0, h1, l1;
        packsplit(v.x, v.y, h0, l0);
        packsplit(v.z, v.w, h1, l1);
        int p0 = c4 >> 1;
        uint32_t* r = QS + row * 72;
        r[permw(p0)]          = h0;
        r[permw(p0 + 1)]      = h1;
        r[32 + permw(p0)]     = l0;
        r[32 + permw(p0 + 1)] = l1;
    }

    float Oacc[8][4];
#pragma unroll
    for (int nt = 0; nt < 8; nt++)
#pragma unroll
        for (int i = 0; i < 4; i++) Oacc[nt][i] = 0.f;
    float m0 = -1e30f, m1 = -1e30f, l0s = 0.f, l1s = 0.f;

    const float* brow0 = bias2d + (size_t)(q0 + 16 * wid + grp) * N_;
    const float* brow1 = brow0 + 8 * N_;

    const uint32_t* gKbh = g_Kp + (size_t)bh * 2048 * 64;
    const uint32_t* gVbh = g_Vt + (size_t)bh * 32 * 64 * 64;

    for (int k0 = 0; k0 < N_; k0 += 64) {
        __syncthreads();   // protect KS/VT vs previous iteration's readers

        // ---- copy pre-converted K', V'^T tiles into smem ----
        const uint32_t* gK = gKbh + (size_t)k0 * 64;
        const uint32_t* gV = gVbh + (size_t)(k0 >> 6) * 64 * 64;
#pragma unroll
        for (int p = 0; p < 8; p++) {
            int idx = p * 128 + tid;
            int row = idx >> 4;
            int w4  = (idx & 15) << 2;
            *(uint4*)&KS[row * 72 + w4] = *(const uint4*)&gK[row * 64 + w4];
            *(uint4*)&VT[row * 72 + w4] = *(const uint4*)&gV[row * 64 + w4];
        }
        __syncthreads();

        // ---- S = Q'K'^T via mma (3-term split, merged passes) ----
        float S[8][4];
#pragma unroll
        for (int nt = 0; nt < 8; nt++)
#pragma unroll
            for (int i = 0; i < 4; i++) S[nt][i] = 0.f;

#pragma unroll
        for (int ck = 0; ck < 4; ck++) {
            const uint32_t* q0p = QS + (16 * wid + grp) * 72 + 8 * ck + 2 * qp;
            const uint32_t* q1p = QS + (16 * wid + grp + 8) * 72 + 8 * ck + 2 * qp;
            uint2 hA = *(const uint2*)q0p;
            uint2 hB = *(const uint2*)q1p;
            uint2 lA = *(const uint2*)(q0p + 32);
            uint2 lB = *(const uint2*)(q1p + 32);
            uint32_t ah[4] = {hA.x, hB.x, hA.y, hB.y};
            uint32_t al[4] = {lA.x, lB.x, lA.y, lB.y};
#pragma unroll
            for (int nt = 0; nt < 8; nt++) {
                const uint32_t* kp = KS + (8 * nt + grp) * 72 + 8 * ck + 2 * qp;
                uint2 bh2 = *(const uint2*)kp;
                uint2 bl2 = *(const uint2*)(kp + 32);
                uint32_t bbh[2] = {bh2.x, bh2.y};
                uint32_t bbl[2] = {bl2.x, bl2.y};
                mma16816(S[nt], ah, bbh);
                mma16816(S[nt], al, bbh);
                mma16816(S[nt], ah, bbl);
            }
        }

        // ---- add bias[q,k] - cp[k] ----
#pragma unroll
        for (int nt = 0; nt < 8; nt++) {
            int col = k0 + 8 * nt + 2 * qp;
            float2 cpv = *(const float2*)(cpb + col);
            float2 b0 = *(const float2*)(brow0 + col);
            float2 b1 = *(const float2*)(brow1 + col);
            S[nt][0] += b0.x - cpv.x;
            S[nt][1] += b0.y - cpv.y;
            S[nt][2] += b1.x - cpv.x;
            S[nt][3] += b1.y - cpv.y;
        }

        // ---- online softmax (rows grp, grp+8; quad shuffles over qp) ----
        float mx0 = -1e30f, mx1 = -1e30f;
#pragma unroll
        for (int nt = 0; nt < 8; nt++) {
            mx0 = fmaxf(mx0, fmaxf(S[nt][0], S[nt][1]));
            mx1 = fmaxf(mx1, fmaxf(S[nt][2], S[nt][3]));
        }
        mx0 = fmaxf(mx0, __shfl_xor_sync(0xffffffffu, mx0, 1));
        mx0 = fmaxf(mx0, __shfl_xor_sync(0xffffffffu, mx0, 2));
        mx1 = fmaxf(mx1, __shfl_xor_sync(0xffffffffu, mx1, 1));
        mx1 = fmaxf(mx1, __shfl_xor_sync(0xffffffffu, mx1, 2));
        float mn0 = fmaxf(m0, mx0);
        float mn1 = fmaxf(m1, mx1);
        float a0 = __expf(m0 - mn0);
        float a1 = __expf(m1 - mn1);
        m0 = mn0; m1 = mn1;
        float rs0 = 0.f, rs1 = 0.f;
#pragma unroll
        for (int nt = 0; nt < 8; nt++) {
            S[nt][0] = __expf(S[nt][0] - mn0);
            S[nt][1] = __expf(S[nt][1] - mn0);
            S[nt][2] = __expf(S[nt][2] - mn1);
            S[nt][3] = __expf(S[nt][3] - mn1);
            rs0 += S[nt][0] + S[nt][1];
            rs1 += S[nt][2] + S[nt][3];
        }
        rs0 += __shfl_xor_sync(0xffffffffu, rs0, 1);
        rs0 += __shfl_xor_sync(0xffffffffu, rs0, 2);
        rs1 += __shfl_xor_sync(0xffffffffu, rs1, 1);
        rs1 += __shfl_xor_sync(0xffffffffu, rs1, 2);
        l0s = l0s * a0 + rs0;
        l1s = l1s * a1 + rs1;
#pragma unroll
        for (int nt = 0; nt < 8; nt++) {
            Oacc[nt][0] *= a0; Oacc[nt][1] *= a0;
            Oacc[nt][2] *= a1; Oacc[nt][3] *= a1;
        }

        // ---- pack P fragments (hi + residual lo) ----
        uint32_t Ph[4][4], Pl[4][4];
#pragma unroll
        for (int ck = 0; ck < 4; ck++) {
            int u = 2 * ck, v = u + 1;
            packsplit(S[u][0], S[u][1], Ph[ck][0], Pl[ck][0]);
            packsplit(S[u][2], S[u][3], Ph[ck][1], Pl[ck][1]);
            packsplit(S[v][0], S[v][1], Ph[ck][2], Pl[ck][2]);
            packsplit(S[v][2], S[v][3], Ph[ck][3], Pl[ck][3]);
        }

        // ---- O += P'V' (3-term split; VT stride 72 -> uint2 legal) ----
#pragma unroll
        for (int ck = 0; ck < 4; ck++) {
#pragma unroll
            for (int nt = 0; nt < 8; nt++) {
                const uint32_t* vp = VT + (8 * nt + grp) * 72 + 8 * ck + 2 * qp;
                uint2 vh2 = *(const uint2*)vp;
                uint2 vl2 = *(const uint2*)(vp + 32);
                uint32_t bbh[2] = {vh2.x, vh2.y};
                uint32_t bbl[2] = {vl2.x, vl2.y};
                mma16816(Oacc[nt], Ph[ck], bbh);
                mma16816(Oacc[nt], Pl[ck], bbh);
                mma16816(Oacc[nt], Ph[ck], bbl);
            }
        }
    }

    // ---- epilogue ----
    float inv0 = 1.0f / l0s, inv1 = 1.0f / l1s;
    float* or0 = out + (size_t)(b * N_ + q0 + 16 * wid + grp) * D_ + h * HD_;
    float* or1 = or0 + 8 * D_;
#pragma unroll
    for (int nt = 0; nt < 8; nt++) {
        int c = 8 * nt + 2 * qp;
        float2 v0 = { Oacc[nt][0] * inv0, Oacc[nt][1] * inv0 };
        float2 v1 = { Oacc[nt][2] * inv1, Oacc[nt][3] * inv1 };
        *(float2*)(or0 + c) = v0;
        *(float2*)(or1 + c) = v1;
    }
}

// ---------------------------------------------------------------------------
extern "C" void kernel_launch(void* const* d_in, const int* in_sizes, int n_in,
                              void* d_out, int out_size)
{
    const float* x         = (const float*)d_in[0];
    const float* coords    = (const float*)d_in[1];
    const float* attn_bias = (const float*)d_in[2];
    const float* Wqkv      = (const float*)d_in[3];
    const float* bqkv      = (const float*)d_in[4];
    const float* rel_w     = (const float*)d_in[5];
    float* out = (float*)d_out;

    conv_a_kernel<<<(M_ * 384) / 256, 256>>>(x);
    conv_b_kernel<<<(TD_ / 32) * NKT * 4 / 8, 256>>>(Wqkv);

    qkv_mma_kernel<<<dim3(TD_ / 128, M_ / 128), 256>>>(bqkv);

    // pre-convert K/V once per (bh, k-tile)
    conv_kv_kernel<<<dim3(32, 32), 128>>>();

    coord_kernel<<<(B_ * H_ * N_ + 255) / 256, 256>>>(coords, rel_w);

    const int attn_smem = AT_SMEM_WORDS * 4;   // 55296 B
    cudaFuncSetAttribute(attn_tc_kernel,
                         cudaFuncAttributeMaxDynamicSharedMemorySize, attn_smem);
    attn_tc_kernel<<<dim3(N_ / 64, B_ * H_), 128, attn_smem>>>(attn_bias, out);
}